// round 2
// baseline (speedup 1.0000x reference)
#include <cuda_runtime.h>

#define NA   25
#define NH   38
#define NW   38
#define NHW  1444
#define BMAX 512
#define SIL  0.6f
#define OBJ  5.0f

__constant__ float c_bw[5] = {1.3221f, 3.19275f, 5.05587f, 9.47112f, 11.2364f};
__constant__ float c_bh[5] = {1.73145f, 4.00944f, 8.09892f, 4.84053f, 10.0071f};
__constant__ float c_sc[5] = {0.5f, 0.75f, 1.0f, 1.25f, 1.5f};

struct BP {
    float gl, gr, gtp, gbt;   // gt box edges
    float garea, gw, gh;
    float txt, tyt, twt, tht; // coord targets at the special cell
    int   sidx, best;
};

__device__ BP     g_bp[BMAX];
__device__ double g_part[BMAX * NA];

// sigmoid(x) = 0.5*tanh(0.5x) + 0.5  -> single MUFU tanh.approx
__device__ __forceinline__ float sigf(float x) {
    float t;
    asm("tanh.approx.f32 %0, %1;" : "=f"(t) : "f"(x * 0.5f));
    return fmaf(t, 0.5f, 0.5f);
}

// ---------------------------------------------------------------------------
// Kernel 1: per-batch ground-truth precompute (tiny)
// ---------------------------------------------------------------------------
__global__ void prep_kernel(const float* __restrict__ tgt, int B) {
    int b = blockIdx.x * blockDim.x + threadIdx.x;
    if (b >= B) return;
    float gx = tgt[4 * b + 0] * 38.0f;
    float gy = tgt[4 * b + 1] * 38.0f;
    float gw = tgt[4 * b + 2] * 38.0f;
    float gh = tgt[4 * b + 3] * 38.0f;
    int gi = (int)gx;
    int gj = (int)gy;

    // best anchor = argmax IoU of (0,0,aw,ah) vs (0,0,gw,gh)  (first max wins)
    int best = 0;
    float bestv = -1.0f;
#pragma unroll
    for (int a = 0; a < NA; a++) {
        float aw = c_bw[a % 5] * c_sc[a / 5];
        float ah = c_bh[a % 5] * c_sc[a / 5];
        float inter = fminf(aw, gw) * fminf(ah, gh);
        float u = aw * ah + gw * gh - inter;
        float iou = inter / u;
        if (iou > bestv) { bestv = iou; best = a; }
    }
    float baw = c_bw[best % 5] * c_sc[best / 5];
    float bah = c_bh[best % 5] * c_sc[best / 5];

    BP bp;
    bp.gl = gx - 0.5f * gw; bp.gr = gx + 0.5f * gw;
    bp.gtp = gy - 0.5f * gh; bp.gbt = gy + 0.5f * gh;
    bp.garea = gw * gh; bp.gw = gw; bp.gh = gh;
    bp.txt = gx - (float)gi;
    bp.tyt = gy - (float)gj;
    bp.twt = logf(gw / baw);
    bp.tht = logf(gh / bah);
    bp.sidx = gj * NW + gi;
    bp.best = best;
    g_bp[b] = bp;
}

// ---------------------------------------------------------------------------
// Kernel 2: main streaming reduction. One block per (batch, anchor).
// ---------------------------------------------------------------------------
__global__ void __launch_bounds__(256) main_kernel(const float* __restrict__ pred) {
    const int a = blockIdx.x;
    const int b = blockIdx.y;

    const BP bp = g_bp[b];
    const float aw = c_bw[a % 5] * c_sc[a / 5];
    const float ah = c_bh[a % 5] * c_sc[a / 5];
    const bool isBest = (a == bp.best);

    const float* __restrict__ p = pred + (size_t)(b * NA + a) * 5 * NHW;

    float acc = 0.0f;
    for (int idx = threadIdx.x; idx < NHW; idx += 256) {
        float tx = p[idx];
        float ty = p[idx + NHW];
        float tw = p[idx + 2 * NHW];
        float th = p[idx + 3 * NHW];
        float tc = p[idx + 4 * NHW];

        // h = idx / 38, w = idx % 38 via magic multiply (valid for idx < 1444)
        int h = (idx * 1725) >> 16;
        int w = idx - h * 38;

        float sx = sigf(tx);
        float sy = sigf(ty);
        float pc = sigf(tc);
        float bw = __expf(tw) * aw;
        float bh = __expf(th) * ah;
        float bx = sx + (float)w;
        float by = sy + (float)h;

        // IoU with gt box (division-free threshold test)
        float mx = fminf(bx - 0.5f * bw, bp.gl);
        float Mx = fmaxf(bx + 0.5f * bw, bp.gr);
        float my = fminf(by - 0.5f * bh, bp.gtp);
        float My = fmaxf(by + 0.5f * bh, bp.gbt);
        float cw = bw + bp.gw - (Mx - mx);
        float ch = bh + bp.gh - (My - my);
        float inter = (cw > 0.0f && ch > 0.0f) ? cw * ch : 0.0f;
        float uni = bw * bh + bp.garea - inter;

        float txt = 0.5f, tyt = 0.5f, twt = 0.0f, tht = 0.0f;
        float cm2 = (inter > SIL * uni) ? 0.0f : 1.0f;  // conf_mask^2
        float ct = 0.0f;
        if (isBest && idx == bp.sidx) {   // one cell per batch
            txt = bp.txt; tyt = bp.tyt; twt = bp.twt; tht = bp.tht;
            cm2 = OBJ;
            ct = inter / uni;             // tconf
        }

        float dx = sx - txt;
        float dy = sy - tyt;
        float dw = tw - twt;
        float dh = th - tht;
        float dc = pc - ct;
        acc += 0.5f * (dx * dx + dy * dy + dw * dw + dh * dh + cm2 * (dc * dc));
    }

    // block reduction (warp shuffle + shared), deterministic per block
#pragma unroll
    for (int o = 16; o > 0; o >>= 1)
        acc += __shfl_down_sync(0xffffffffu, acc, o);

    __shared__ float warpS[8];
    if ((threadIdx.x & 31) == 0) warpS[threadIdx.x >> 5] = acc;
    __syncthreads();
    if (threadIdx.x < 8) {
        float v = warpS[threadIdx.x];
#pragma unroll
        for (int o = 4; o > 0; o >>= 1)
            v += __shfl_down_sync(0xffu, v, o);
        if (threadIdx.x == 0)
            g_part[b * NA + a] = (double)v;
    }
}

// ---------------------------------------------------------------------------
// Kernel 3: deterministic final sum of 12800 double partials -> float scalar
// ---------------------------------------------------------------------------
__global__ void finalize_kernel(float* __restrict__ out, int n) {
    __shared__ double sh[256];
    double s = 0.0;
    for (int i = threadIdx.x; i < n; i += 256) s += g_part[i];
    sh[threadIdx.x] = s;
    __syncthreads();
#pragma unroll
    for (int o = 128; o > 0; o >>= 1) {
        if (threadIdx.x < o) sh[threadIdx.x] += sh[threadIdx.x + o];
        __syncthreads();
    }
    if (threadIdx.x == 0) out[0] = (float)sh[0];
}

extern "C" void kernel_launch(void* const* d_in, const int* in_sizes, int n_in,
                              void* d_out, int out_size) {
    const float* pred = (const float*)d_in[0];
    const float* tgt  = (const float*)d_in[1];
    int B = in_sizes[1] / 4;                 // 512
    if (B > BMAX) B = BMAX;

    prep_kernel<<<(B + 255) / 256, 256>>>(tgt, B);
    dim3 grid(NA, B);
    main_kernel<<<grid, 256>>>(pred);
    finalize_kernel<<<1, 256>>>((float*)d_out, B * NA);
}

// round 3
// speedup vs baseline: 1.3319x; 1.3319x over previous
#include <cuda_runtime.h>

#define NA   25
#define NHW  1444
#define NV   361          // NHW / 4 (float4 units per plane)
#define BMAX 512

__constant__ float c_bw[5] = {1.3221f, 3.19275f, 5.05587f, 9.47112f, 11.2364f};
__constant__ float c_bh[5] = {1.73145f, 4.00944f, 8.09892f, 4.84053f, 10.0071f};
__constant__ float c_sc[5] = {0.5f, 0.75f, 1.0f, 1.25f, 1.5f};

struct BP {
    float gl, gr, gt, gb;     // gt box edges
    float gw, gh, garea;
    float txt, tyt, twt, tht; // coord targets at the special cell
    int   sidx, best;
};

__device__ __align__(16) float g_part[BMAX * NA];

__device__ __forceinline__ float tanhapx(float x) {
    float t;
    asm("tanh.approx.f32 %0, %1;" : "=f"(t) : "f"(x));
    return t;
}

struct CO { float dense, inter, uni, sx, sy, pc; };

// Per-cell evaluation. hw/hh are HALF widths (0.5*anchor folded into lhw/lhh).
__device__ __forceinline__ CO cell_eval(
    float tx, float ty, float tw, float th, float tc,
    float cxw, float cyh, float lhw, float lhh,
    float gl, float gr, float gt, float gb,
    float gw, float gh, float garea)
{
    const float L2E = 1.4426950408889634f;
    float tX = tanhapx(0.5f * tx);
    float tY = tanhapx(0.5f * ty);
    float tC = tanhapx(0.5f * tc);
    float bx = fmaf(tX, 0.5f, cxw);            // sigmoid(tx) + w
    float by = fmaf(tY, 0.5f, cyh);
    float hw = exp2f(fmaf(tw, L2E, lhw));      // 0.5 * aw * exp(tw)
    float hh = exp2f(fmaf(th, L2E, lhh));
    float mx = fminf(bx - hw, gl);
    float Mx = fmaxf(bx + hw, gr);
    float my = fminf(by - hh, gt);
    float My = fmaxf(by + hh, gb);
    float cw = fmaf(hw, 2.0f, gw) - (Mx - mx);
    float ch = fmaf(hh, 2.0f, gh) - (My - my);
    float inter = (cw > 0.0f && ch > 0.0f) ? cw * ch : 0.0f;
    float uni   = fmaf(hw * hh, 4.0f, garea) - inter;
    bool noobj  = fmaf(uni, -0.6f, inter) <= 0.0f;   // !(iou > 0.6)
    float pc = fmaf(tC, 0.5f, 0.5f);
    float confsq = noobj ? pc * pc : 0.0f;
    float s1 = fmaf(tX, tX, tY * tY);          // (2*dx)^2 + (2*dy)^2
    float s2 = fmaf(tw, tw, th * th);          // dw^2 + dh^2 (targets 0)
    CO o;
    o.dense = fmaf(s1, 0.125f, fmaf(s2, 0.5f, 0.5f * confsq));
    o.inter = inter; o.uni = uni;
    o.sx = fmaf(tX, 0.5f, 0.5f);
    o.sy = fmaf(tY, 0.5f, 0.5f);
    o.pc = pc;
    return o;
}

__global__ void __launch_bounds__(128) main_kernel(
    const float* __restrict__ pred, const float* __restrict__ tgt)
{
    const int a = blockIdx.x;
    const int b = blockIdx.y;

    __shared__ BP sbp;
    __shared__ float ws[4];

    if (threadIdx.x == 0) {
        float gx = tgt[4 * b + 0] * 38.0f;
        float gy = tgt[4 * b + 1] * 38.0f;
        float gw = tgt[4 * b + 2] * 38.0f;
        float gh = tgt[4 * b + 3] * 38.0f;
        int gi = (int)gx;
        int gj = (int)gy;
        float garea = gw * gh;

        // division-free argmax over anchor IoUs (first max wins)
        int best = 0;
        float binter = 0.0f, buni = 1.0f;
#pragma unroll
        for (int ai = 0; ai < NA; ai++) {
            float aw = c_bw[ai % 5] * c_sc[ai / 5];
            float ah = c_bh[ai % 5] * c_sc[ai / 5];
            float in_ = fminf(aw, gw) * fminf(ah, gh);
            float un  = aw * ah + garea - in_;
            if (ai == 0 || in_ * buni > binter * un) {
                binter = in_; buni = un; best = ai;
            }
        }
        float baw = c_bw[best % 5] * c_sc[best / 5];
        float bah = c_bh[best % 5] * c_sc[best / 5];

        BP bp;
        bp.gl = gx - 0.5f * gw;  bp.gr = gx + 0.5f * gw;
        bp.gt = gy - 0.5f * gh;  bp.gb = gy + 0.5f * gh;
        bp.gw = gw; bp.gh = gh; bp.garea = garea;
        bp.txt = gx - (float)gi;
        bp.tyt = gy - (float)gj;
        bp.twt = logf(gw / baw);
        bp.tht = logf(gh / bah);
        bp.sidx = gj * 38 + gi;
        bp.best = best;
        sbp = bp;
    }
    __syncthreads();
    const BP bp = sbp;

    int am = a - (a / 5) * 5;
    float aw = c_bw[am] * c_sc[a / 5];
    float ah = c_bh[am] * c_sc[a / 5];
    float lhw = __log2f(0.5f * aw);
    float lhh = __log2f(0.5f * ah);

    const float4* __restrict__ p4 =
        (const float4*)(pred + (size_t)(b * NA + a) * 5 * NHW);

    float acc = 0.0f;
    for (int v = threadIdx.x; v < NV; v += 128) {
        float4 X = p4[v];
        float4 Y = p4[v + NV];
        float4 W = p4[v + 2 * NV];
        float4 H = p4[v + 3 * NV];
        float4 C = p4[v + 4 * NV];
        float xa[4] = {X.x, X.y, X.z, X.w};
        float ya[4] = {Y.x, Y.y, Y.z, Y.w};
        float wa[4] = {W.x, W.y, W.z, W.w};
        float ha[4] = {H.x, H.y, H.z, H.w};
        float ca[4] = {C.x, C.y, C.z, C.w};
        int base = 4 * v;
#pragma unroll
        for (int k = 0; k < 4; k++) {
            int idx = base + k;
            int hh_ = (idx * 1725) >> 16;      // idx / 38
            int ww_ = idx - hh_ * 38;
            CO o = cell_eval(xa[k], ya[k], wa[k], ha[k], ca[k],
                             (float)ww_ + 0.5f, (float)hh_ + 0.5f,
                             lhw, lhh,
                             bp.gl, bp.gr, bp.gt, bp.gb,
                             bp.gw, bp.gh, bp.garea);
            acc += o.dense;
        }
    }

    // special-cell correction: one block per batch owns it
    if (threadIdx.x == 0 && a == bp.best) {
        int idx = bp.sidx;
        const float* p = pred + (size_t)(b * NA + a) * 5 * NHW;
        float tx = __ldg(p + idx);
        float ty = __ldg(p + idx + NHW);
        float tw = __ldg(p + idx + 2 * NHW);
        float th = __ldg(p + idx + 3 * NHW);
        float tc = __ldg(p + idx + 4 * NHW);
        int hh_ = (idx * 1725) >> 16;
        int ww_ = idx - hh_ * 38;
        CO o = cell_eval(tx, ty, tw, th, tc,
                         (float)ww_ + 0.5f, (float)hh_ + 0.5f,
                         lhw, lhh,
                         bp.gl, bp.gr, bp.gt, bp.gb,
                         bp.gw, bp.gh, bp.garea);
        float dx = o.sx - bp.txt;
        float dy = o.sy - bp.tyt;
        float dw = tw - bp.twt;
        float dh = th - bp.tht;
        float tconf = o.inter / o.uni;
        float dc = o.pc - tconf;
        float truec = 0.5f * (dx * dx + dy * dy + dw * dw + dh * dh)
                    + 2.5f * (dc * dc);               // OBJECT_SCALE/2
        acc += truec - o.dense;
    }

    // deterministic block reduction (4 warps)
#pragma unroll
    for (int off = 16; off > 0; off >>= 1)
        acc += __shfl_down_sync(0xffffffffu, acc, off);
    if ((threadIdx.x & 31) == 0) ws[threadIdx.x >> 5] = acc;
    __syncthreads();
    if (threadIdx.x == 0)
        g_part[b * NA + a] = (ws[0] + ws[1]) + (ws[2] + ws[3]);
}

__global__ void finalize_kernel(float* __restrict__ out, int n4) {
    __shared__ double sh[256];
    const float4* __restrict__ pp = (const float4*)g_part;
    double s = 0.0;
    for (int i = threadIdx.x; i < n4; i += 256) {
        float4 v = pp[i];
        s += ((double)v.x + (double)v.y) + ((double)v.z + (double)v.w);
    }
    sh[threadIdx.x] = s;
    __syncthreads();
#pragma unroll
    for (int off = 128; off > 0; off >>= 1) {
        if (threadIdx.x < off) sh[threadIdx.x] += sh[threadIdx.x + off];
        __syncthreads();
    }
    if (threadIdx.x == 0) out[0] = (float)sh[0];
}

extern "C" void kernel_launch(void* const* d_in, const int* in_sizes, int n_in,
                              void* d_out, int out_size) {
    const float* pred = (const float*)d_in[0];
    const float* tgt  = (const float*)d_in[1];
    int B = in_sizes[1] / 4;
    if (B > BMAX) B = BMAX;

    dim3 grid(NA, B);
    main_kernel<<<grid, 128>>>(pred, tgt);
    finalize_kernel<<<1, 256>>>((float*)d_out, (B * NA) / 4);
}